// round 1
// baseline (speedup 1.0000x reference)
#include <cuda_runtime.h>
#include <cstdint>

// Problem shape (fixed by the dataset)
constexpr int B_N    = 256;
constexpr int T_N    = 16384;
constexpr int CHUNKS = 8;                      // chunks per sample -> 2048 blocks
constexpr int TPB    = 256;
constexpr int CHUNK_ELEMS = T_N / CHUNKS;      // 2048 elems per block
constexpr int QUADS_PER_THREAD = CHUNK_ELEMS / 4 / TPB;  // 2

constexpr float EPS_C    = 1e-4f;
// SR / (T * TARGET_FACTOR) = 22050 / (16384*256)
constexpr float INV_CLIP = 22050.0f / (16384.0f * 256.0f);

// Per-(sample,chunk) partials: {cls_sum, num_pos, reg_sum, K}
__device__ float g_partial[B_N * CHUNKS * 4];

__device__ __forceinline__ float cls_term(float c, bool lab) {
    c = fminf(fmaxf(c, EPS_C), 1.0f - EPS_C);
    // lab: 0.25*(1-c)^5 * -log(c) ; else: 0.75*c^5 * -log(1-c)
    const float p  = lab ? (1.0f - c) : c;
    const float lg = lab ? __logf(c) : __logf(1.0f - c);
    const float a  = lab ? 0.25f : 0.75f;
    const float p2 = p * p;
    return a * (p2 * p2 * p) * (-lg);
}

__global__ __launch_bounds__(TPB) void partial_kernel(
    const float* __restrict__ cls,   // [B, T, 2]
    const float* __restrict__ reg,   // [B, T, 1]
    const float* __restrict__ ann)   // [B, 3, T]
{
    const int b     = blockIdx.y;
    const int chunk = blockIdx.x;
    const int tbase = chunk * CHUNK_ELEMS;

    const float* __restrict__ ann0 = ann + (size_t)b * 3 * T_N;
    const float* __restrict__ ann1 = ann0 + T_N;
    const float* __restrict__ ann2 = ann0 + 2 * T_N;
    const float* __restrict__ clsb = cls + (size_t)b * T_N * 2;
    const float* __restrict__ regb = reg + (size_t)b * T_N;

    float cls_sum = 0.0f;
    float reg_sum = 0.0f;
    int   np = 0;   // num_pos: original beat mask count (classification normalizer)
    int   K  = 0;   // fixed-pos count (regression normalizer)

    #pragma unroll
    for (int j = 0; j < QUADS_PER_THREAD; ++j) {
        const int q = threadIdx.x + j * TPB;   // quad index within chunk
        const int t = tbase + q * 4;

        const float4 a0 = *reinterpret_cast<const float4*>(ann0 + t);
        const float4 a1 = *reinterpret_cast<const float4*>(ann1 + t);
        const float4 a2 = *reinterpret_cast<const float4*>(ann2 + t);
        const float4 cA = *reinterpret_cast<const float4*>(clsb + 2 * t);
        const float4 cB = *reinterpret_cast<const float4*>(clsb + 2 * t + 4);
        const float4 r  = *reinterpret_cast<const float4*>(regb + t);

        const float a0v[4] = {a0.x, a0.y, a0.z, a0.w};
        const float a1v[4] = {a1.x, a1.y, a1.z, a1.w};
        const float a2v[4] = {a2.x, a2.y, a2.z, a2.w};
        const float cv[8]  = {cA.x, cA.y, cA.z, cA.w, cB.x, cB.y, cB.z, cB.w};
        const float rv[4]  = {r.x,  r.y,  r.z,  r.w};

        const bool last_quad = (t + 4 == T_N);

        #pragma unroll
        for (int e = 0; e < 4; ++e) {
            const bool beat = (a0v[e] != 0.0f);
            const bool down = (a1v[e] != 0.0f);
            np += beat ? 1 : 0;
            cls_sum += cls_term(cv[2 * e],     beat && down);
            cls_sum += cls_term(cv[2 * e + 1], beat && !down);

            // regression anchor mask with end-fix:
            //   pos[T-2] |= ann0[T-1];  pos[T-1] = 0
            bool pos = beat;
            if (last_quad) {
                if (e == 2) pos = beat || (a0v[3] != 0.0f);
                if (e == 3) pos = false;
            }
            if (pos) {
                ++K;
                const float rn    = a2v[e] * INV_CLIP;
                const float rnext = (e < 3) ? rv[e + 1] : __ldg(regb + t + 4);
                const float dl = rn - rv[e];
                const float dr = rn - rnext;
                reg_sum += 0.5f * (dl * dl + dr * dr);
            }
        }
    }

    // Block reduce four values (np/K as float)
    float v0 = cls_sum, v1 = (float)np, v2 = reg_sum, v3 = (float)K;
    #pragma unroll
    for (int o = 16; o > 0; o >>= 1) {
        v0 += __shfl_down_sync(0xFFFFFFFFu, v0, o);
        v1 += __shfl_down_sync(0xFFFFFFFFu, v1, o);
        v2 += __shfl_down_sync(0xFFFFFFFFu, v2, o);
        v3 += __shfl_down_sync(0xFFFFFFFFu, v3, o);
    }
    __shared__ float sm[4][TPB / 32];
    const int warp = threadIdx.x >> 5;
    const int lane = threadIdx.x & 31;
    if (lane == 0) {
        sm[0][warp] = v0; sm[1][warp] = v1; sm[2][warp] = v2; sm[3][warp] = v3;
    }
    __syncthreads();
    if (threadIdx.x == 0) {
        float s0 = 0.f, s1 = 0.f, s2 = 0.f, s3 = 0.f;
        #pragma unroll
        for (int w = 0; w < TPB / 32; ++w) {
            s0 += sm[0][w]; s1 += sm[1][w]; s2 += sm[2][w]; s3 += sm[3][w];
        }
        float* dst = &g_partial[((size_t)b * CHUNKS + chunk) * 4];
        dst[0] = s0; dst[1] = s1; dst[2] = s2; dst[3] = s3;
    }
}

__global__ __launch_bounds__(B_N) void final_kernel(float* __restrict__ out) {
    const int b = threadIdx.x;
    float sc = 0.f, sn = 0.f, sr = 0.f, sk = 0.f;
    #pragma unroll
    for (int ch = 0; ch < CHUNKS; ++ch) {
        const float* p = &g_partial[((size_t)b * CHUNKS + ch) * 4];
        sc += p[0]; sn += p[1]; sr += p[2]; sk += p[3];
    }
    float cls_loss = sc / sn * 10.0f;
    float reg_loss = sr / sk * 10.0f;

    #pragma unroll
    for (int o = 16; o > 0; o >>= 1) {
        cls_loss += __shfl_down_sync(0xFFFFFFFFu, cls_loss, o);
        reg_loss += __shfl_down_sync(0xFFFFFFFFu, reg_loss, o);
    }
    __shared__ float sA[B_N / 32], sB[B_N / 32];
    const int warp = threadIdx.x >> 5;
    const int lane = threadIdx.x & 31;
    if (lane == 0) { sA[warp] = cls_loss; sB[warp] = reg_loss; }
    __syncthreads();
    if (threadIdx.x == 0) {
        float tc = 0.f, tr = 0.f;
        #pragma unroll
        for (int w = 0; w < B_N / 32; ++w) { tc += sA[w]; tr += sB[w]; }
        out[0] = tc * (1.0f / (float)B_N);
        out[1] = tr * (1.0f / (float)B_N);
    }
}

extern "C" void kernel_launch(void* const* d_in, const int* in_sizes, int n_in,
                              void* d_out, int out_size) {
    const float* cls = (const float*)d_in[0];  // [B, T, 2]
    const float* reg = (const float*)d_in[1];  // [B, T, 1]
    const float* ann = (const float*)d_in[2];  // [B, 3, T]
    float* out = (float*)d_out;                // [2]

    dim3 grid(CHUNKS, B_N);
    partial_kernel<<<grid, TPB>>>(cls, reg, ann);
    final_kernel<<<1, B_N>>>(out);
}